// round 14
// baseline (speedup 1.0000x reference)
#include <cuda_runtime.h>
#include <cstdint>

#define NN 100000
#define NE 1600000
#define BN_EPS 1e-5f

typedef unsigned long long u64;

// ---------------- device scratch (no allocations allowed) ----------------
__device__ __align__(16) float g_p[NN * 64];     // x @ (W0_top - W0_bot) * s0
__device__ __align__(16) float g_q[NN * 64];     // x @ W0_bot * s0
__device__ __align__(16) float g_seg[NN * 64];   // segment sums
__device__ __align__(16) float g_cnt[NN];        // edge counts per dst
__device__ __align__(16) float g_z[NN * 128];    // y @ We0 per node
__device__ __align__(16) float g_w0a[16 * 64];
__device__ __align__(16) float g_w0b[16 * 64];
__device__ __align__(16) float g_W1[64 * 64];
__device__ __align__(16) float g_W2[64 * 64];
__device__ __align__(16) float g_B[3 * 64];      // folded biases B0,B1,B2

// ---------------- packed f32x2 helpers (sm_103a) ----------------
__device__ __forceinline__ u64 fma2(u64 a, u64 b, u64 c) {
  u64 d;
  asm("fma.rn.f32x2 %0, %1, %2, %3;" : "=l"(d) : "l"(a), "l"(b), "l"(c));
  return d;
}
__device__ __forceinline__ u64 dup2(float x) {
  u64 d;
  asm("mov.b64 %0, {%1, %1};" : "=l"(d) : "f"(x));
  return d;
}
__device__ __forceinline__ float2 unpk2(u64 a) {
  float2 f;
  asm("mov.b64 {%0, %1}, %2;" : "=f"(f.x), "=f"(f.y) : "l"(a));
  return f;
}

// ---------------- K0: fold BN into weights ----------------
__global__ void fold_kernel(
    const float* __restrict__ w0, const float* __restrict__ b0,
    const float* __restrict__ g0, const float* __restrict__ be0,
    const float* __restrict__ m0, const float* __restrict__ v0,
    const float* __restrict__ w1, const float* __restrict__ b1,
    const float* __restrict__ g1, const float* __restrict__ be1,
    const float* __restrict__ m1, const float* __restrict__ v1,
    const float* __restrict__ w2, const float* __restrict__ b2,
    const float* __restrict__ g2, const float* __restrict__ be2,
    const float* __restrict__ m2, const float* __restrict__ v2) {
  int j = threadIdx.x;  // 0..63
  float s0 = g0[j] * rsqrtf(v0[j] + BN_EPS);
  g_B[j] = (b0[j] - m0[j]) * s0 + be0[j];
  for (int i = 0; i < 16; i++) {
    float top = w0[i * 64 + j];
    float bot = w0[(16 + i) * 64 + j];
    g_w0a[i * 64 + j] = (top - bot) * s0;  // coefficient of x[dst]
    g_w0b[i * 64 + j] = bot * s0;          // coefficient of x[src]
  }
  float s1 = g1[j] * rsqrtf(v1[j] + BN_EPS);
  g_B[64 + j] = (b1[j] - m1[j]) * s1 + be1[j];
  for (int i = 0; i < 64; i++) g_W1[i * 64 + j] = w1[i * 64 + j] * s1;
  float s2 = g2[j] * rsqrtf(v2[j] + BN_EPS);
  g_B[128 + j] = (b2[j] - m2[j]) * s2 + be2[j];
  for (int i = 0; i < 64; i++) g_W2[i * 64 + j] = w2[i * 64 + j] * s2;
}

// ---------------- K1: per-node p,q precompute ----------------
__global__ void pq_kernel(const float* __restrict__ x) {
  int n = blockIdx.x * 4 + threadIdx.y;
  if (n >= NN) return;
  int j = threadIdx.x;
  float p = 0.f, q = 0.f;
#pragma unroll
  for (int i = 0; i < 16; i++) {
    float xi = __ldg(&x[n * 16 + i]);
    p = fmaf(xi, g_w0a[i * 64 + j], p);
    q = fmaf(xi, g_w0b[i * 64 + j], q);
  }
  g_p[n * 64 + j] = p;
  g_q[n * 64 + j] = q;
}

// ---------------- K2: per-edge MLP (layers 0..2) + atomic scatter ----------------
// 128 threads/block, 1 edge/thread. h in shared (stride-128), acc in 32 packed
// f32x2 registers, weights broadcast from shared as b64 pairs, FFMA2 mainloop.
__global__ void __launch_bounds__(128) edge_mlp_kernel(const int* __restrict__ ei) {
  extern __shared__ float sm[];
  float* sW1 = sm;                 // 4096
  float* sW2 = sm + 4096;          // 4096
  float* sB = sm + 8192;           // 192
  float* sH = sm + 8192 + 192;     // 64 * 128

  int tid = threadIdx.x;
  for (int i = tid; i < 4096; i += 128) {
    sW1[i] = g_W1[i];
    sW2[i] = g_W2[i];
  }
  if (tid < 64) {
    sB[tid] = g_B[tid];
    sB[64 + tid] = g_B[64 + tid];
    sB[128 + tid] = g_B[128 + tid];
  }
  __syncthreads();

  int e = blockIdx.x * 128 + tid;
  if (e >= NE) return;
  int s = ei[e];
  int d = ei[NE + e];

  // layer 0: p[dst] + q[src] + B0, relu -> sH
  const float4* pd = (const float4*)(g_p + (size_t)d * 64);
  const float4* qs = (const float4*)(g_q + (size_t)s * 64);
  const float4* bb0 = (const float4*)sB;
#pragma unroll
  for (int jj = 0; jj < 16; jj++) {
    float4 a = pd[jj];
    float4 b = qs[jj];
    float4 c = bb0[jj];
    sH[(4 * jj + 0) * 128 + tid] = fmaxf(a.x + b.x + c.x, 0.f);
    sH[(4 * jj + 1) * 128 + tid] = fmaxf(a.y + b.y + c.y, 0.f);
    sH[(4 * jj + 2) * 128 + tid] = fmaxf(a.z + b.z + c.z, 0.f);
    sH[(4 * jj + 3) * 128 + tid] = fmaxf(a.w + b.w + c.w, 0.f);
  }

  u64 acc[32];

  // ---- layer 1 (packed f32x2) ----
  {
    const u64* b1v = (const u64*)(sB + 64);
#pragma unroll
    for (int j = 0; j < 32; j++) acc[j] = b1v[j];
  }
#pragma unroll 2
  for (int k = 0; k < 64; k++) {
    u64 hk2 = dup2(sH[k * 128 + tid]);
    const ulonglong2* wr = (const ulonglong2*)(sW1 + k * 64);
#pragma unroll
    for (int jj = 0; jj < 16; jj++) {
      ulonglong2 w = wr[jj];
      acc[2 * jj + 0] = fma2(hk2, w.x, acc[2 * jj + 0]);
      acc[2 * jj + 1] = fma2(hk2, w.y, acc[2 * jj + 1]);
    }
  }
#pragma unroll
  for (int j = 0; j < 32; j++) {
    float2 f = unpk2(acc[j]);
    sH[(2 * j + 0) * 128 + tid] = fmaxf(f.x, 0.f);
    sH[(2 * j + 1) * 128 + tid] = fmaxf(f.y, 0.f);
  }

  // ---- layer 2 (packed f32x2) ----
  {
    const u64* b2v = (const u64*)(sB + 128);
#pragma unroll
    for (int j = 0; j < 32; j++) acc[j] = b2v[j];
  }
#pragma unroll 2
  for (int k = 0; k < 64; k++) {
    u64 hk2 = dup2(sH[k * 128 + tid]);
    const ulonglong2* wr = (const ulonglong2*)(sW2 + k * 64);
#pragma unroll
    for (int jj = 0; jj < 16; jj++) {
      ulonglong2 w = wr[jj];
      acc[2 * jj + 0] = fma2(hk2, w.x, acc[2 * jj + 0]);
      acc[2 * jj + 1] = fma2(hk2, w.y, acc[2 * jj + 1]);
    }
  }

  // relu + vectorized reduction scatter into seg[dst]
  float* sg = g_seg + (size_t)d * 64;
#pragma unroll
  for (int jj = 0; jj < 8; jj++) {
    float2 f0 = unpk2(acc[4 * jj + 0]);
    float2 f1 = unpk2(acc[4 * jj + 1]);
    float2 f2 = unpk2(acc[4 * jj + 2]);
    float2 f3 = unpk2(acc[4 * jj + 3]);
    asm volatile("red.global.add.v4.f32 [%0], {%1,%2,%3,%4};"
                 :: "l"(sg + 8 * jj), "f"(fmaxf(f0.x, 0.f)), "f"(fmaxf(f0.y, 0.f)),
                    "f"(fmaxf(f1.x, 0.f)), "f"(fmaxf(f1.y, 0.f))
                 : "memory");
    asm volatile("red.global.add.v4.f32 [%0], {%1,%2,%3,%4};"
                 :: "l"(sg + 8 * jj + 4), "f"(fmaxf(f2.x, 0.f)), "f"(fmaxf(f2.y, 0.f)),
                    "f"(fmaxf(f3.x, 0.f)), "f"(fmaxf(f3.y, 0.f))
                 : "memory");
  }
  atomicAdd(&g_cnt[d], 1.0f);
}

// ---------------- K3: per-node finalize + z = relu(concat(agg,x)) @ We0 ----------------
// 1024 threads: 8 nodes/block, we0 (40KB) staged in shared.
__global__ void __launch_bounds__(1024) node_z_kernel(const float* __restrict__ x,
                                                      const float* __restrict__ we0) {
  __shared__ float sW[80 * 128];
  __shared__ float sY[8][80];
  int tid = threadIdx.y * 128 + threadIdx.x;
  for (int i = tid; i < 80 * 128; i += 1024) sW[i] = we0[i];

  int n = blockIdx.x * 8 + threadIdx.y;
  int j = threadIdx.x;
  if (n < NN) {
    if (j < 64) {
      float inv = 1.f / fmaxf(g_cnt[n], 1.f);
      sY[threadIdx.y][j] = fmaxf(g_seg[(size_t)n * 64 + j] * inv, 0.f);
    } else if (j < 80) {
      sY[threadIdx.y][j] = fmaxf(x[n * 16 + (j - 64)], 0.f);
    }
  }
  __syncthreads();
  if (n >= NN) return;
  float z = 0.f;
#pragma unroll 10
  for (int k = 0; k < 80; k++)
    z = fmaf(sY[threadIdx.y][k], sW[k * 128 + j], z);
  g_z[(size_t)n * 128 + j] = z;
}

// ---------------- K4: per-edge output head ----------------
__global__ void edge_out_kernel(const int* __restrict__ ei,
                                const float* __restrict__ bee0,
                                const float* __restrict__ we1,
                                const float* __restrict__ bee1,
                                float* __restrict__ out) {
  int t = blockIdx.x * 256 + threadIdx.x;
  int e = t >> 2;
  int l = t & 3;
  if (e >= NE) return;
  int s = ei[e];
  int d = ei[NE + e];
  const float4* zs = (const float4*)(g_z + (size_t)s * 128);
  const float4* zd = (const float4*)(g_z + (size_t)d * 128);
  const float4* bv = (const float4*)bee0;
  const float4* wv = (const float4*)we1;
  float acc = 0.f;
#pragma unroll
  for (int i = 0; i < 8; i++) {
    int idx = l * 8 + i;
    float4 a = zs[idx];
    float4 b = zd[idx];
    float4 c = __ldg(&bv[idx]);
    float4 w = __ldg(&wv[idx]);
    acc = fmaf(fmaxf(a.x - b.x + c.x, 0.f), w.x, acc);
    acc = fmaf(fmaxf(a.y - b.y + c.y, 0.f), w.y, acc);
    acc = fmaf(fmaxf(a.z - b.z + c.z, 0.f), w.z, acc);
    acc = fmaf(fmaxf(a.w - b.w + c.w, 0.f), w.w, acc);
  }
  acc += __shfl_xor_sync(0xffffffffu, acc, 1);
  acc += __shfl_xor_sync(0xffffffffu, acc, 2);
  if (l == 0) {
    float v = acc + __ldg(&bee1[0]);
    out[e] = 1.f / (1.f + __expf(-v));
  }
}

// ---------------- launch ----------------
extern "C" void kernel_launch(void* const* d_in, const int* in_sizes, int n_in,
                              void* d_out, int out_size) {
  const float* x = (const float*)d_in[0];
  const int* ei = (const int*)d_in[1];
  const float* w0 = (const float*)d_in[2];
  const float* b0 = (const float*)d_in[3];
  const float* g0 = (const float*)d_in[4];
  const float* be0 = (const float*)d_in[5];
  const float* m0 = (const float*)d_in[6];
  const float* v0 = (const float*)d_in[7];
  const float* w1 = (const float*)d_in[8];
  const float* b1 = (const float*)d_in[9];
  const float* g1 = (const float*)d_in[10];
  const float* be1 = (const float*)d_in[11];
  const float* m1 = (const float*)d_in[12];
  const float* v1 = (const float*)d_in[13];
  const float* w2 = (const float*)d_in[14];
  const float* b2 = (const float*)d_in[15];
  const float* g2 = (const float*)d_in[16];
  const float* be2 = (const float*)d_in[17];
  const float* m2 = (const float*)d_in[18];
  const float* v2 = (const float*)d_in[19];
  const float* we0 = (const float*)d_in[20];
  const float* bee0 = (const float*)d_in[21];
  const float* we1 = (const float*)d_in[22];
  const float* bee1 = (const float*)d_in[23];
  float* out = (float*)d_out;

  void* segp = nullptr;
  void* cntp = nullptr;
  cudaGetSymbolAddress(&segp, g_seg);
  cudaGetSymbolAddress(&cntp, g_cnt);
  cudaMemsetAsync(segp, 0, (size_t)NN * 64 * sizeof(float));
  cudaMemsetAsync(cntp, 0, (size_t)NN * sizeof(float));

  fold_kernel<<<1, 64>>>(w0, b0, g0, be0, m0, v0,
                         w1, b1, g1, be1, m1, v1,
                         w2, b2, g2, be2, m2, v2);

  pq_kernel<<<NN / 4, dim3(64, 4)>>>(x);

  const int smem_bytes = (4096 + 4096 + 192 + 64 * 128) * (int)sizeof(float);  // 66304
  cudaFuncSetAttribute(edge_mlp_kernel,
                       cudaFuncAttributeMaxDynamicSharedMemorySize, smem_bytes);
  edge_mlp_kernel<<<NE / 128, 128, smem_bytes>>>(ei);

  node_z_kernel<<<NN / 8, dim3(128, 8)>>>(x, we0);

  edge_out_kernel<<<NE / 64, 256>>>(ei, bee0, we1, bee1, out);
}

// round 15
// speedup vs baseline: 1.1152x; 1.1152x over previous
#include <cuda_runtime.h>
#include <cstdint>

#define NN 100000
#define NE 1600000
#define BN_EPS 1e-5f

// ---------------- device scratch (no allocations allowed) ----------------
__device__ __align__(16) float g_p[NN * 64];     // x @ (W0_top - W0_bot) * s0
__device__ __align__(16) float g_q[NN * 64];     // x @ W0_bot * s0
__device__ __align__(16) float g_seg[NN * 64];   // segment sums
__device__ __align__(16) float g_cnt[NN];        // edge counts per dst
__device__ __align__(16) float g_z[NN * 128];    // y @ We0 per node
__device__ __align__(16) float g_w0a[16 * 64];
__device__ __align__(16) float g_w0b[16 * 64];
__device__ __align__(16) float g_W1[64 * 64];
__device__ __align__(16) float g_W2[64 * 64];
__device__ __align__(16) float g_B[3 * 64];      // folded biases B0,B1,B2

// ---------------- K0: fold BN into weights ----------------
__global__ void fold_kernel(
    const float* __restrict__ w0, const float* __restrict__ b0,
    const float* __restrict__ g0, const float* __restrict__ be0,
    const float* __restrict__ m0, const float* __restrict__ v0,
    const float* __restrict__ w1, const float* __restrict__ b1,
    const float* __restrict__ g1, const float* __restrict__ be1,
    const float* __restrict__ m1, const float* __restrict__ v1,
    const float* __restrict__ w2, const float* __restrict__ b2,
    const float* __restrict__ g2, const float* __restrict__ be2,
    const float* __restrict__ m2, const float* __restrict__ v2) {
  int j = threadIdx.x;  // 0..63
  float s0 = g0[j] * rsqrtf(v0[j] + BN_EPS);
  g_B[j] = (b0[j] - m0[j]) * s0 + be0[j];
  for (int i = 0; i < 16; i++) {
    float top = w0[i * 64 + j];
    float bot = w0[(16 + i) * 64 + j];
    g_w0a[i * 64 + j] = (top - bot) * s0;  // coefficient of x[dst]
    g_w0b[i * 64 + j] = bot * s0;          // coefficient of x[src]
  }
  float s1 = g1[j] * rsqrtf(v1[j] + BN_EPS);
  g_B[64 + j] = (b1[j] - m1[j]) * s1 + be1[j];
  for (int i = 0; i < 64; i++) g_W1[i * 64 + j] = w1[i * 64 + j] * s1;
  float s2 = g2[j] * rsqrtf(v2[j] + BN_EPS);
  g_B[128 + j] = (b2[j] - m2[j]) * s2 + be2[j];
  for (int i = 0; i < 64; i++) g_W2[i * 64 + j] = w2[i * 64 + j] * s2;
}

// ---------------- no-op spacer so ncu's skip-5 lands on edge_mlp ----------------
__global__ void noop_kernel() {}

// ---------------- K1: per-node p,q precompute ----------------
__global__ void pq_kernel(const float* __restrict__ x) {
  int n = blockIdx.x * 4 + threadIdx.y;
  if (n >= NN) return;
  int j = threadIdx.x;
  float p = 0.f, q = 0.f;
#pragma unroll
  for (int i = 0; i < 16; i++) {
    float xi = __ldg(&x[n * 16 + i]);
    p = fmaf(xi, g_w0a[i * 64 + j], p);
    q = fmaf(xi, g_w0b[i * 64 + j], q);
  }
  g_p[n * 64 + j] = p;
  g_q[n * 64 + j] = q;
}

// ---------------- K2: per-edge MLP (layers 0..2) + atomic scatter ----------------
// 256 threads/block, 1 edge/thread. h in shared (stride-256, conflict-free),
// acc[64] in registers, weights broadcast from shared. 2 blocks/SM (16 warps).
__global__ void __launch_bounds__(256, 2) edge_mlp_kernel(const int* __restrict__ ei) {
  extern __shared__ float sm[];
  float* sW1 = sm;                 // 4096
  float* sW2 = sm + 4096;          // 4096
  float* sB = sm + 8192;           // 192
  float* sH = sm + 8192 + 192;     // 64 * 256

  int tid = threadIdx.x;
  for (int i = tid; i < 4096; i += 256) {
    sW1[i] = g_W1[i];
    sW2[i] = g_W2[i];
  }
  if (tid < 192) sB[tid] = g_B[tid];
  __syncthreads();

  int e = blockIdx.x * 256 + tid;
  if (e >= NE) return;
  int s = ei[e];
  int d = ei[NE + e];

  // layer 0: p[dst] + q[src] + B0, relu -> sH
  const float4* pd = (const float4*)(g_p + (size_t)d * 64);
  const float4* qs = (const float4*)(g_q + (size_t)s * 64);
  const float4* bb0 = (const float4*)sB;
#pragma unroll
  for (int jj = 0; jj < 16; jj++) {
    float4 a = pd[jj];
    float4 b = qs[jj];
    float4 c = bb0[jj];
    sH[(4 * jj + 0) * 256 + tid] = fmaxf(a.x + b.x + c.x, 0.f);
    sH[(4 * jj + 1) * 256 + tid] = fmaxf(a.y + b.y + c.y, 0.f);
    sH[(4 * jj + 2) * 256 + tid] = fmaxf(a.z + b.z + c.z, 0.f);
    sH[(4 * jj + 3) * 256 + tid] = fmaxf(a.w + b.w + c.w, 0.f);
  }

  float acc[64];

  // ---- layer 1 ----
#pragma unroll
  for (int j = 0; j < 64; j++) acc[j] = sB[64 + j];
#pragma unroll 2
  for (int k = 0; k < 64; k++) {
    float hk = sH[k * 256 + tid];
    const float4* wr = (const float4*)(sW1 + k * 64);
#pragma unroll
    for (int jj = 0; jj < 16; jj++) {
      float4 w = wr[jj];
      acc[4 * jj + 0] = fmaf(hk, w.x, acc[4 * jj + 0]);
      acc[4 * jj + 1] = fmaf(hk, w.y, acc[4 * jj + 1]);
      acc[4 * jj + 2] = fmaf(hk, w.z, acc[4 * jj + 2]);
      acc[4 * jj + 3] = fmaf(hk, w.w, acc[4 * jj + 3]);
    }
  }
#pragma unroll
  for (int k = 0; k < 64; k++) sH[k * 256 + tid] = fmaxf(acc[k], 0.f);

  // ---- layer 2 ----
#pragma unroll
  for (int j = 0; j < 64; j++) acc[j] = sB[128 + j];
#pragma unroll 2
  for (int k = 0; k < 64; k++) {
    float hk = sH[k * 256 + tid];
    const float4* wr = (const float4*)(sW2 + k * 64);
#pragma unroll
    for (int jj = 0; jj < 16; jj++) {
      float4 w = wr[jj];
      acc[4 * jj + 0] = fmaf(hk, w.x, acc[4 * jj + 0]);
      acc[4 * jj + 1] = fmaf(hk, w.y, acc[4 * jj + 1]);
      acc[4 * jj + 2] = fmaf(hk, w.z, acc[4 * jj + 2]);
      acc[4 * jj + 3] = fmaf(hk, w.w, acc[4 * jj + 3]);
    }
  }

  // relu + vectorized reduction scatter into seg[dst]
  float* sg = g_seg + (size_t)d * 64;
#pragma unroll
  for (int jj = 0; jj < 16; jj++) {
    float v0 = fmaxf(acc[4 * jj + 0], 0.f);
    float v1 = fmaxf(acc[4 * jj + 1], 0.f);
    float v2 = fmaxf(acc[4 * jj + 2], 0.f);
    float v3 = fmaxf(acc[4 * jj + 3], 0.f);
    asm volatile("red.global.add.v4.f32 [%0], {%1,%2,%3,%4};"
                 :: "l"(sg + 4 * jj), "f"(v0), "f"(v1), "f"(v2), "f"(v3)
                 : "memory");
  }
  atomicAdd(&g_cnt[d], 1.0f);
}

// ---------------- K3: per-node finalize + z = relu(concat(agg,x)) @ We0 ----------------
// 128 threads (j), 16 nodes/block. Weight value lives in a register and is
// applied to 16 node-accumulators; y read as broadcast LDS.128.
__global__ void __launch_bounds__(128) node_z_kernel(const float* __restrict__ x,
                                                     const float* __restrict__ we0) {
  __shared__ __align__(16) float sY[16][80];
  int tid = threadIdx.x;
  int nb = blockIdx.x * 16;

  // stage y = relu(concat(agg, x)) for 16 nodes
  for (int i = tid; i < 16 * 80; i += 128) {
    int r = i / 80;
    int k = i % 80;
    int n = nb + r;
    float v;
    if (k < 64) {
      float inv = 1.f / fmaxf(g_cnt[n], 1.f);
      v = g_seg[(size_t)n * 64 + k] * inv;
    } else {
      v = x[n * 16 + (k - 64)];
    }
    sY[r][k] = fmaxf(v, 0.f);
  }
  __syncthreads();

  float acc[16];
#pragma unroll
  for (int r = 0; r < 16; r++) acc[r] = 0.f;

#pragma unroll 4
  for (int k4 = 0; k4 < 20; k4++) {
    float w0 = __ldg(&we0[(4 * k4 + 0) * 128 + tid]);
    float w1 = __ldg(&we0[(4 * k4 + 1) * 128 + tid]);
    float w2 = __ldg(&we0[(4 * k4 + 2) * 128 + tid]);
    float w3 = __ldg(&we0[(4 * k4 + 3) * 128 + tid]);
#pragma unroll
    for (int r = 0; r < 16; r++) {
      float4 y = *(const float4*)&sY[r][4 * k4];
      acc[r] = fmaf(y.x, w0, acc[r]);
      acc[r] = fmaf(y.y, w1, acc[r]);
      acc[r] = fmaf(y.z, w2, acc[r]);
      acc[r] = fmaf(y.w, w3, acc[r]);
    }
  }
#pragma unroll
  for (int r = 0; r < 16; r++)
    g_z[(size_t)(nb + r) * 128 + tid] = acc[r];
}

// ---------------- K4: per-edge output head ----------------
__global__ void edge_out_kernel(const int* __restrict__ ei,
                                const float* __restrict__ bee0,
                                const float* __restrict__ we1,
                                const float* __restrict__ bee1,
                                float* __restrict__ out) {
  int t = blockIdx.x * 256 + threadIdx.x;
  int e = t >> 2;
  int l = t & 3;
  if (e >= NE) return;
  int s = ei[e];
  int d = ei[NE + e];
  const float4* zs = (const float4*)(g_z + (size_t)s * 128);
  const float4* zd = (const float4*)(g_z + (size_t)d * 128);
  const float4* bv = (const float4*)bee0;
  const float4* wv = (const float4*)we1;
  float acc = 0.f;
#pragma unroll
  for (int i = 0; i < 8; i++) {
    int idx = l * 8 + i;
    float4 a = zs[idx];
    float4 b = zd[idx];
    float4 c = __ldg(&bv[idx]);
    float4 w = __ldg(&wv[idx]);
    acc = fmaf(fmaxf(a.x - b.x + c.x, 0.f), w.x, acc);
    acc = fmaf(fmaxf(a.y - b.y + c.y, 0.f), w.y, acc);
    acc = fmaf(fmaxf(a.z - b.z + c.z, 0.f), w.z, acc);
    acc = fmaf(fmaxf(a.w - b.w + c.w, 0.f), w.w, acc);
  }
  acc += __shfl_xor_sync(0xffffffffu, acc, 1);
  acc += __shfl_xor_sync(0xffffffffu, acc, 2);
  if (l == 0) {
    float v = acc + __ldg(&bee1[0]);
    out[e] = 1.f / (1.f + __expf(-v));
  }
}

// ---------------- launch ----------------
extern "C" void kernel_launch(void* const* d_in, const int* in_sizes, int n_in,
                              void* d_out, int out_size) {
  const float* x = (const float*)d_in[0];
  const int* ei = (const int*)d_in[1];
  const float* w0 = (const float*)d_in[2];
  const float* b0 = (const float*)d_in[3];
  const float* g0 = (const float*)d_in[4];
  const float* be0 = (const float*)d_in[5];
  const float* m0 = (const float*)d_in[6];
  const float* v0 = (const float*)d_in[7];
  const float* w1 = (const float*)d_in[8];
  const float* b1 = (const float*)d_in[9];
  const float* g1 = (const float*)d_in[10];
  const float* be1 = (const float*)d_in[11];
  const float* m1 = (const float*)d_in[12];
  const float* v1 = (const float*)d_in[13];
  const float* w2 = (const float*)d_in[14];
  const float* b2 = (const float*)d_in[15];
  const float* g2 = (const float*)d_in[16];
  const float* be2 = (const float*)d_in[17];
  const float* m2 = (const float*)d_in[18];
  const float* v2 = (const float*)d_in[19];
  const float* we0 = (const float*)d_in[20];
  const float* bee0 = (const float*)d_in[21];
  const float* we1 = (const float*)d_in[22];
  const float* bee1 = (const float*)d_in[23];
  float* out = (float*)d_out;

  void* segp = nullptr;
  void* cntp = nullptr;
  cudaGetSymbolAddress(&segp, g_seg);
  cudaGetSymbolAddress(&cntp, g_cnt);
  cudaMemsetAsync(segp, 0, (size_t)NN * 64 * sizeof(float));
  cudaMemsetAsync(cntp, 0, (size_t)NN * sizeof(float));

  fold_kernel<<<1, 64>>>(w0, b0, g0, be0, m0, v0,
                         w1, b1, g1, be1, m1, v1,
                         w2, b2, g2, be2, m2, v2);

  pq_kernel<<<NN / 4, dim3(64, 4)>>>(x);

  noop_kernel<<<1, 32>>>();  // spacer: makes edge_mlp the 6th node for ncu -s 5

  const int smem_bytes = (4096 + 4096 + 192 + 64 * 256) * (int)sizeof(float);  // 99072
  cudaFuncSetAttribute(edge_mlp_kernel,
                       cudaFuncAttributeMaxDynamicSharedMemorySize, smem_bytes);
  edge_mlp_kernel<<<NE / 256, 256, smem_bytes>>>(ei);

  node_z_kernel<<<NN / 16, 128>>>(x, we0);

  edge_out_kernel<<<NE / 64, 256>>>(ei, bee0, we1, bee1, out);
}

// round 16
// speedup vs baseline: 1.3806x; 1.2379x over previous
#include <cuda_runtime.h>
#include <cstdint>

#define NN 100000
#define NE 1600000
#define BN_EPS 1e-5f

// ---------------- device scratch (no allocations allowed) ----------------
__device__ __align__(16) float g_p[NN * 64];     // x @ (W0_top - W0_bot) * s0
__device__ __align__(16) float g_q[NN * 64];     // x @ W0_bot * s0
__device__ __align__(16) float g_seg[NN * 64];   // segment sums
__device__ __align__(16) float g_cnt[NN];        // edge counts per dst
__device__ __align__(16) float g_z[NN * 128];    // y @ We0 per node
__device__ __align__(16) float g_w0a[16 * 64];
__device__ __align__(16) float g_w0b[16 * 64];
__device__ __align__(16) float g_W1[64 * 64];
__device__ __align__(16) float g_W2[64 * 64];
__device__ __align__(16) float g_B[3 * 64];      // folded biases B0,B1,B2

// ---------------- K0: fold BN into weights ----------------
__global__ void fold_kernel(
    const float* __restrict__ w0, const float* __restrict__ b0,
    const float* __restrict__ g0, const float* __restrict__ be0,
    const float* __restrict__ m0, const float* __restrict__ v0,
    const float* __restrict__ w1, const float* __restrict__ b1,
    const float* __restrict__ g1, const float* __restrict__ be1,
    const float* __restrict__ m1, const float* __restrict__ v1,
    const float* __restrict__ w2, const float* __restrict__ b2,
    const float* __restrict__ g2, const float* __restrict__ be2,
    const float* __restrict__ m2, const float* __restrict__ v2) {
  int j = threadIdx.x;  // 0..63
  float s0 = g0[j] * rsqrtf(v0[j] + BN_EPS);
  g_B[j] = (b0[j] - m0[j]) * s0 + be0[j];
  for (int i = 0; i < 16; i++) {
    float top = w0[i * 64 + j];
    float bot = w0[(16 + i) * 64 + j];
    g_w0a[i * 64 + j] = (top - bot) * s0;  // coefficient of x[dst]
    g_w0b[i * 64 + j] = bot * s0;          // coefficient of x[src]
  }
  float s1 = g1[j] * rsqrtf(v1[j] + BN_EPS);
  g_B[64 + j] = (b1[j] - m1[j]) * s1 + be1[j];
  for (int i = 0; i < 64; i++) g_W1[i * 64 + j] = w1[i * 64 + j] * s1;
  float s2 = g2[j] * rsqrtf(v2[j] + BN_EPS);
  g_B[128 + j] = (b2[j] - m2[j]) * s2 + be2[j];
  for (int i = 0; i < 64; i++) g_W2[i * 64 + j] = w2[i * 64 + j] * s2;
}

// ---------------- no-op spacer so ncu's skip-5 lands on edge_mlp ----------------
__global__ void noop_kernel() {}

// ---------------- K1: per-node p,q precompute ----------------
__global__ void pq_kernel(const float* __restrict__ x) {
  int n = blockIdx.x * 4 + threadIdx.y;
  if (n >= NN) return;
  int j = threadIdx.x;
  float p = 0.f, q = 0.f;
#pragma unroll
  for (int i = 0; i < 16; i++) {
    float xi = __ldg(&x[n * 16 + i]);
    p = fmaf(xi, g_w0a[i * 64 + j], p);
    q = fmaf(xi, g_w0b[i * 64 + j], q);
  }
  g_p[n * 64 + j] = p;
  g_q[n * 64 + j] = q;
}

// ---------------- K2: per-edge MLP + scatter, register-tiled GEMM ----------------
// Block = 256 edges. Layer 0: 1 edge/thread into sH[j][e] (row stride 256).
// Layers 1-2: thread tile = 4 edges x 16 outputs (eg = tid&63, jg = tid>>6).
// Per k: 1 LDS.128 (h of 4 edges) + 4 broadcast LDS.128 (16 weights) + 64 FMA.
__global__ void __launch_bounds__(256, 2) edge_mlp_kernel(const int* __restrict__ ei) {
  extern __shared__ float sm[];
  float* sW1 = sm;                 // 4096
  float* sW2 = sm + 4096;          // 4096
  float* sB = sm + 8192;           // 192
  float* sH = sm + 8192 + 192;     // 64 * 256

  int tid = threadIdx.x;
  for (int i = tid; i < 4096; i += 256) {
    sW1[i] = g_W1[i];
    sW2[i] = g_W2[i];
  }
  if (tid < 192) sB[tid] = g_B[tid];
  __syncthreads();

  // ---- layer 0: one edge per thread ----
  {
    int e = blockIdx.x * 256 + tid;
    int s = ei[e];
    int d = ei[NE + e];
    const float4* pd = (const float4*)(g_p + (size_t)d * 64);
    const float4* qs = (const float4*)(g_q + (size_t)s * 64);
    const float4* bb0 = (const float4*)sB;
#pragma unroll
    for (int jj = 0; jj < 16; jj++) {
      float4 a = pd[jj];
      float4 b = qs[jj];
      float4 c = bb0[jj];
      sH[(4 * jj + 0) * 256 + tid] = fmaxf(a.x + b.x + c.x, 0.f);
      sH[(4 * jj + 1) * 256 + tid] = fmaxf(a.y + b.y + c.y, 0.f);
      sH[(4 * jj + 2) * 256 + tid] = fmaxf(a.z + b.z + c.z, 0.f);
      sH[(4 * jj + 3) * 256 + tid] = fmaxf(a.w + b.w + c.w, 0.f);
    }
  }
  __syncthreads();

  int eg = tid & 63;   // edge group: edges eg*4 .. eg*4+3
  int jg = tid >> 6;   // output group: j in [jg*16, jg*16+16)
  float acc[64];       // acc[e*16 + j]

  // ---- layer 1 ----
#pragma unroll
  for (int j = 0; j < 16; j++) {
    float b = sB[64 + jg * 16 + j];
    acc[0 * 16 + j] = b; acc[1 * 16 + j] = b;
    acc[2 * 16 + j] = b; acc[3 * 16 + j] = b;
  }
#pragma unroll 2
  for (int k = 0; k < 64; k++) {
    float4 h4 = *(const float4*)&sH[k * 256 + eg * 4];
    const float4* wr = (const float4*)(sW1 + k * 64 + jg * 16);
    float4 w0 = wr[0], w1 = wr[1], w2 = wr[2], w3 = wr[3];
#pragma unroll
    for (int e = 0; e < 4; e++) {
      float h = (e == 0) ? h4.x : (e == 1) ? h4.y : (e == 2) ? h4.z : h4.w;
      acc[e * 16 + 0]  = fmaf(h, w0.x, acc[e * 16 + 0]);
      acc[e * 16 + 1]  = fmaf(h, w0.y, acc[e * 16 + 1]);
      acc[e * 16 + 2]  = fmaf(h, w0.z, acc[e * 16 + 2]);
      acc[e * 16 + 3]  = fmaf(h, w0.w, acc[e * 16 + 3]);
      acc[e * 16 + 4]  = fmaf(h, w1.x, acc[e * 16 + 4]);
      acc[e * 16 + 5]  = fmaf(h, w1.y, acc[e * 16 + 5]);
      acc[e * 16 + 6]  = fmaf(h, w1.z, acc[e * 16 + 6]);
      acc[e * 16 + 7]  = fmaf(h, w1.w, acc[e * 16 + 7]);
      acc[e * 16 + 8]  = fmaf(h, w2.x, acc[e * 16 + 8]);
      acc[e * 16 + 9]  = fmaf(h, w2.y, acc[e * 16 + 9]);
      acc[e * 16 + 10] = fmaf(h, w2.z, acc[e * 16 + 10]);
      acc[e * 16 + 11] = fmaf(h, w2.w, acc[e * 16 + 11]);
      acc[e * 16 + 12] = fmaf(h, w3.x, acc[e * 16 + 12]);
      acc[e * 16 + 13] = fmaf(h, w3.y, acc[e * 16 + 13]);
      acc[e * 16 + 14] = fmaf(h, w3.z, acc[e * 16 + 14]);
      acc[e * 16 + 15] = fmaf(h, w3.w, acc[e * 16 + 15]);
    }
  }
  __syncthreads();  // all reads of layer-0 sH done before overwrite

  // write relu(layer1) back to sH[j][e], 16 STS.128
#pragma unroll
  for (int j = 0; j < 16; j++) {
    float4 v;
    v.x = fmaxf(acc[0 * 16 + j], 0.f);
    v.y = fmaxf(acc[1 * 16 + j], 0.f);
    v.z = fmaxf(acc[2 * 16 + j], 0.f);
    v.w = fmaxf(acc[3 * 16 + j], 0.f);
    *(float4*)&sH[(jg * 16 + j) * 256 + eg * 4] = v;
  }
  __syncthreads();

  // ---- layer 2 ----
#pragma unroll
  for (int j = 0; j < 16; j++) {
    float b = sB[128 + jg * 16 + j];
    acc[0 * 16 + j] = b; acc[1 * 16 + j] = b;
    acc[2 * 16 + j] = b; acc[3 * 16 + j] = b;
  }
#pragma unroll 2
  for (int k = 0; k < 64; k++) {
    float4 h4 = *(const float4*)&sH[k * 256 + eg * 4];
    const float4* wr = (const float4*)(sW2 + k * 64 + jg * 16);
    float4 w0 = wr[0], w1 = wr[1], w2 = wr[2], w3 = wr[3];
#pragma unroll
    for (int e = 0; e < 4; e++) {
      float h = (e == 0) ? h4.x : (e == 1) ? h4.y : (e == 2) ? h4.z : h4.w;
      acc[e * 16 + 0]  = fmaf(h, w0.x, acc[e * 16 + 0]);
      acc[e * 16 + 1]  = fmaf(h, w0.y, acc[e * 16 + 1]);
      acc[e * 16 + 2]  = fmaf(h, w0.z, acc[e * 16 + 2]);
      acc[e * 16 + 3]  = fmaf(h, w0.w, acc[e * 16 + 3]);
      acc[e * 16 + 4]  = fmaf(h, w1.x, acc[e * 16 + 4]);
      acc[e * 16 + 5]  = fmaf(h, w1.y, acc[e * 16 + 5]);
      acc[e * 16 + 6]  = fmaf(h, w1.z, acc[e * 16 + 6]);
      acc[e * 16 + 7]  = fmaf(h, w1.w, acc[e * 16 + 7]);
      acc[e * 16 + 8]  = fmaf(h, w2.x, acc[e * 16 + 8]);
      acc[e * 16 + 9]  = fmaf(h, w2.y, acc[e * 16 + 9]);
      acc[e * 16 + 10] = fmaf(h, w2.z, acc[e * 16 + 10]);
      acc[e * 16 + 11] = fmaf(h, w2.w, acc[e * 16 + 11]);
      acc[e * 16 + 12] = fmaf(h, w3.x, acc[e * 16 + 12]);
      acc[e * 16 + 13] = fmaf(h, w3.y, acc[e * 16 + 13]);
      acc[e * 16 + 14] = fmaf(h, w3.z, acc[e * 16 + 14]);
      acc[e * 16 + 15] = fmaf(h, w3.w, acc[e * 16 + 15]);
    }
  }

  // ---- relu + reduction scatter straight from the register tile ----
#pragma unroll
  for (int e = 0; e < 4; e++) {
    int edge = blockIdx.x * 256 + eg * 4 + e;
    int d = ei[NE + edge];
    float* sg = g_seg + (size_t)d * 64 + jg * 16;
#pragma unroll
    for (int jj = 0; jj < 4; jj++) {
      float v0 = fmaxf(acc[e * 16 + 4 * jj + 0], 0.f);
      float v1 = fmaxf(acc[e * 16 + 4 * jj + 1], 0.f);
      float v2 = fmaxf(acc[e * 16 + 4 * jj + 2], 0.f);
      float v3 = fmaxf(acc[e * 16 + 4 * jj + 3], 0.f);
      asm volatile("red.global.add.v4.f32 [%0], {%1,%2,%3,%4};"
                   :: "l"(sg + 4 * jj), "f"(v0), "f"(v1), "f"(v2), "f"(v3)
                   : "memory");
    }
    if (jg == 0) atomicAdd(&g_cnt[d], 1.0f);
  }
}

// ---------------- K3: per-node finalize + z = relu(concat(agg,x)) @ We0 ----------------
__global__ void __launch_bounds__(128) node_z_kernel(const float* __restrict__ x,
                                                     const float* __restrict__ we0) {
  __shared__ __align__(16) float sY[16][80];
  int tid = threadIdx.x;
  int nb = blockIdx.x * 16;

  for (int i = tid; i < 16 * 80; i += 128) {
    int r = i / 80;
    int k = i % 80;
    int n = nb + r;
    float v;
    if (k < 64) {
      float inv = 1.f / fmaxf(g_cnt[n], 1.f);
      v = g_seg[(size_t)n * 64 + k] * inv;
    } else {
      v = x[n * 16 + (k - 64)];
    }
    sY[r][k] = fmaxf(v, 0.f);
  }
  __syncthreads();

  float acc[16];
#pragma unroll
  for (int r = 0; r < 16; r++) acc[r] = 0.f;

#pragma unroll 4
  for (int k4 = 0; k4 < 20; k4++) {
    float w0 = __ldg(&we0[(4 * k4 + 0) * 128 + tid]);
    float w1 = __ldg(&we0[(4 * k4 + 1) * 128 + tid]);
    float w2 = __ldg(&we0[(4 * k4 + 2) * 128 + tid]);
    float w3 = __ldg(&we0[(4 * k4 + 3) * 128 + tid]);
#pragma unroll
    for (int r = 0; r < 16; r++) {
      float4 y = *(const float4*)&sY[r][4 * k4];
      acc[r] = fmaf(y.x, w0, acc[r]);
      acc[r] = fmaf(y.y, w1, acc[r]);
      acc[r] = fmaf(y.z, w2, acc[r]);
      acc[r] = fmaf(y.w, w3, acc[r]);
    }
  }
#pragma unroll
  for (int r = 0; r < 16; r++)
    g_z[(size_t)(nb + r) * 128 + tid] = acc[r];
}

// ---------------- K4: per-edge output head ----------------
__global__ void edge_out_kernel(const int* __restrict__ ei,
                                const float* __restrict__ bee0,
                                const float* __restrict__ we1,
                                const float* __restrict__ bee1,
                                float* __restrict__ out) {
  int t = blockIdx.x * 256 + threadIdx.x;
  int e = t >> 2;
  int l = t & 3;
  if (e >= NE) return;
  int s = ei[e];
  int d = ei[NE + e];
  const float4* zs = (const float4*)(g_z + (size_t)s * 128);
  const float4* zd = (const float4*)(g_z + (size_t)d * 128);
  const float4* bv = (const float4*)bee0;
  const float4* wv = (const float4*)we1;
  float acc = 0.f;
#pragma unroll
  for (int i = 0; i < 8; i++) {
    int idx = l * 8 + i;
    float4 a = zs[idx];
    float4 b = zd[idx];
    float4 c = __ldg(&bv[idx]);
    float4 w = __ldg(&wv[idx]);
    acc = fmaf(fmaxf(a.x - b.x + c.x, 0.f), w.x, acc);
    acc = fmaf(fmaxf(a.y - b.y + c.y, 0.f), w.y, acc);
    acc = fmaf(fmaxf(a.z - b.z + c.z, 0.f), w.z, acc);
    acc = fmaf(fmaxf(a.w - b.w + c.w, 0.f), w.w, acc);
  }
  acc += __shfl_xor_sync(0xffffffffu, acc, 1);
  acc += __shfl_xor_sync(0xffffffffu, acc, 2);
  if (l == 0) {
    float v = acc + __ldg(&bee1[0]);
    out[e] = 1.f / (1.f + __expf(-v));
  }
}

// ---------------- launch ----------------
extern "C" void kernel_launch(void* const* d_in, const int* in_sizes, int n_in,
                              void* d_out, int out_size) {
  const float* x = (const float*)d_in[0];
  const int* ei = (const int*)d_in[1];
  const float* w0 = (const float*)d_in[2];
  const float* b0 = (const float*)d_in[3];
  const float* g0 = (const float*)d_in[4];
  const float* be0 = (const float*)d_in[5];
  const float* m0 = (const float*)d_in[6];
  const float* v0 = (const float*)d_in[7];
  const float* w1 = (const float*)d_in[8];
  const float* b1 = (const float*)d_in[9];
  const float* g1 = (const float*)d_in[10];
  const float* be1 = (const float*)d_in[11];
  const float* m1 = (const float*)d_in[12];
  const float* v1 = (const float*)d_in[13];
  const float* w2 = (const float*)d_in[14];
  const float* b2 = (const float*)d_in[15];
  const float* g2 = (const float*)d_in[16];
  const float* be2 = (const float*)d_in[17];
  const float* m2 = (const float*)d_in[18];
  const float* v2 = (const float*)d_in[19];
  const float* we0 = (const float*)d_in[20];
  const float* bee0 = (const float*)d_in[21];
  const float* we1 = (const float*)d_in[22];
  const float* bee1 = (const float*)d_in[23];
  float* out = (float*)d_out;

  void* segp = nullptr;
  void* cntp = nullptr;
  cudaGetSymbolAddress(&segp, g_seg);
  cudaGetSymbolAddress(&cntp, g_cnt);
  cudaMemsetAsync(segp, 0, (size_t)NN * 64 * sizeof(float));
  cudaMemsetAsync(cntp, 0, (size_t)NN * sizeof(float));

  fold_kernel<<<1, 64>>>(w0, b0, g0, be0, m0, v0,
                         w1, b1, g1, be1, m1, v1,
                         w2, b2, g2, be2, m2, v2);

  pq_kernel<<<NN / 4, dim3(64, 4)>>>(x);

  noop_kernel<<<1, 32>>>();  // spacer: keeps edge_mlp as the 6th node for ncu -s 5

  const int smem_bytes = (4096 + 4096 + 192 + 64 * 256) * (int)sizeof(float);  // 99072
  cudaFuncSetAttribute(edge_mlp_kernel,
                       cudaFuncAttributeMaxDynamicSharedMemorySize, smem_bytes);
  edge_mlp_kernel<<<NE / 256, 256, smem_bytes>>>(ei);

  node_z_kernel<<<NN / 16, 128>>>(x, we0);

  edge_out_kernel<<<NE / 64, 256>>>(ei, bee0, we1, bee1, out);
}